// round 1
// baseline (speedup 1.0000x reference)
#include <cuda_runtime.h>
#include <math.h>
#include <stdint.h>

// Problem constants (shapes are fixed by the dataset)
#define LNF 128      // feat dim
#define SS  32       // stat dim
#define CC  10       // classes
#define NPQ 2048     // P(1024) || Q(1024) per node
#define MAXV 50000
#define MU_OVER_S (0.9f / 32.0f)

// -------- static device scratch (no runtime allocation allowed) --------
__device__ float g_PQ[(size_t)MAXV * NPQ];   // ~410 MB: P[v]=PQ[v][0:1024], Q[v]=PQ[v][1024:2048]
__device__ float g_W2[LNF * NPQ];            // packed [128 x 2048] = [Wxi_top | Wxi_bot]
__device__ float g_R[MAXV * SS];             // R[v] = tanh(feat[v]@Wrou + brou)
__device__ float g_hacc[MAXV * SS];          // accumulates sum_e A_e @ R[u_e]  (== M_v @ R_v)
__device__ int   g_cnt[MAXV];                // out-degree counts over X_Node

// ---------------- pack W2: W2[k][j] = Wxi[k][j] (j<1024) else Wxi[k+128][j-1024] ----------------
__global__ void pack_w2_kernel(const float* __restrict__ Wxi) {
    int idx = blockIdx.x * blockDim.x + threadIdx.x;
    if (idx < LNF * NPQ) {
        int k = idx / NPQ, j = idx - k * NPQ;
        g_W2[idx] = (j < 1024) ? Wxi[k * 1024 + j]
                               : Wxi[(k + LNF) * 1024 + (j - 1024)];
    }
}

// ---------------- zero accumulators ----------------
__global__ void zero_kernel(int V) {
    int idx = blockIdx.x * blockDim.x + threadIdx.x;
    if (idx < V * SS) g_hacc[idx] = 0.0f;
    if (idx < V)      g_cnt[idx]  = 0;
}

// ---------------- GEMM: g_PQ[M x 2048] = feat[M x 128] @ g_W2[128 x 2048] ----------------
#define BM 128
#define BN 128
#define BK 16
#define TM 8
#define TN 8

__global__ __launch_bounds__(256) void gemm_pq_kernel(const float* __restrict__ A, int M) {
    __shared__ float As[BK][BM + 4];   // transposed A tile, padded
    __shared__ float Bs[BK][BN];

    const int bn = blockIdx.x;            // 2048/128 = 16 tiles
    const int bm = blockIdx.y;
    const int tid = threadIdx.x;
    const int tx = tid % 16;              // N direction
    const int ty = tid / 16;              // M direction
    const int row0 = bm * BM;
    const int col0 = bn * BN;

    float acc[TM][TN];
#pragma unroll
    for (int i = 0; i < TM; ++i)
#pragma unroll
        for (int j = 0; j < TN; ++j) acc[i][j] = 0.0f;

    for (int kt = 0; kt < LNF; kt += BK) {
        // A tile: 128 rows x 16 k (512 float4, 2 per thread), store transposed
#pragma unroll
        for (int l = 0; l < 2; ++l) {
            int lin = tid + l * 256;          // 0..511
            int r = lin >> 2;                 // row in tile 0..127
            int kq = lin & 3;                 // which float4 along k
            int grow = row0 + r;
            float4 v = make_float4(0.f, 0.f, 0.f, 0.f);
            if (grow < M)
                v = *(const float4*)(A + (size_t)grow * LNF + kt + kq * 4);
            As[kq * 4 + 0][r] = v.x;
            As[kq * 4 + 1][r] = v.y;
            As[kq * 4 + 2][r] = v.z;
            As[kq * 4 + 3][r] = v.w;
        }
        // B tile: 16 k x 128 n (512 float4, 2 per thread)
#pragma unroll
        for (int l = 0; l < 2; ++l) {
            int lin = tid + l * 256;
            int r = lin >> 5;                 // k row 0..15
            int cq = lin & 31;                // float4 within 128 cols
            float4 v = *(const float4*)(g_W2 + (size_t)(kt + r) * NPQ + col0 + cq * 4);
            *(float4*)&Bs[r][cq * 4] = v;
        }
        __syncthreads();

#pragma unroll
        for (int kk = 0; kk < BK; ++kk) {
            float ra[TM], rb[TN];
#pragma unroll
            for (int i = 0; i < TM; ++i) ra[i] = As[kk][ty * TM + i];
#pragma unroll
            for (int j = 0; j < TN; ++j) rb[j] = Bs[kk][tx * TN + j];
#pragma unroll
            for (int i = 0; i < TM; ++i)
#pragma unroll
                for (int j = 0; j < TN; ++j)
                    acc[i][j] = fmaf(ra[i], rb[j], acc[i][j]);
        }
        __syncthreads();
    }

#pragma unroll
    for (int i = 0; i < TM; ++i) {
        int grow = row0 + ty * TM + i;
        if (grow < M) {
#pragma unroll
            for (int j = 0; j < TN; j += 4) {
                float4 v = make_float4(acc[i][j], acc[i][j + 1], acc[i][j + 2], acc[i][j + 3]);
                *(float4*)(g_PQ + (size_t)grow * NPQ + col0 + tx * TN + j) = v;
            }
        }
    }
}

// ---------------- R[v] = tanh(feat[v] @ Wrou + brou), one warp per node ----------------
__global__ __launch_bounds__(256) void r_kernel(const float* __restrict__ feat,
                                                const float* __restrict__ Wrou,
                                                const float* __restrict__ brou, int V) {
    __shared__ float Ws[LNF * SS];     // 16 KB
    __shared__ float fr[8][LNF];       // per-warp feature row
    int tid = threadIdx.x;
    for (int i = tid; i < LNF * SS; i += 256) Ws[i] = Wrou[i];
    __syncthreads();

    int warp = tid >> 5, lane = tid & 31;
    int v = blockIdx.x * 8 + warp;
    if (v >= V) return;

    for (int k = lane; k < LNF; k += 32) fr[warp][k] = feat[(size_t)v * LNF + k];
    __syncwarp();

    float s = 0.0f;
#pragma unroll
    for (int k = 0; k < LNF; ++k) s = fmaf(fr[warp][k], Ws[k * SS + lane], s);
    g_R[v * SS + lane] = tanhf(s + brou[lane]);
}

// ---------------- edge kernel: per edge, A_e @ R[u] scattered into g_hacc[u] ----------------
// A_e[i][j] = tanh(P[u][i*32+j] + Q[v][i*32+j] + bxi[i*32+j]) * (MU/S)/deg_e
__global__ __launch_bounds__(256) void edge_kernel(const int* __restrict__ Xn,
                                                   const int* __restrict__ Xe,
                                                   const float* __restrict__ dg,
                                                   const float* __restrict__ bxi, int E) {
    int e = blockIdx.x;
    if (e >= E) return;
    int u = Xn[e];
    int v = Xe[e];
    float scale = MU_OVER_S / dg[e];

    __shared__ float rs[SS];
    int tid = threadIdx.x;
    if (tid < SS) rs[tid] = g_R[u * SS + tid];
    __syncthreads();

    // thread tid covers 4 consecutive elements: linear idx = tid*4 -> i = tid/8, j = (tid%8)*4 + k
    const float4 p  = ((const float4*)(g_PQ + (size_t)u * NPQ))[tid];
    const float4 q  = ((const float4*)(g_PQ + (size_t)v * NPQ + 1024))[tid];
    const float4 bx = ((const float4*)bxi)[tid];
    int jq = (tid & 7) * 4;

    float partial =
          tanhf(p.x + q.x + bx.x) * rs[jq + 0]
        + tanhf(p.y + q.y + bx.y) * rs[jq + 1]
        + tanhf(p.z + q.z + bx.z) * rs[jq + 2]
        + tanhf(p.w + q.w + bx.w) * rs[jq + 3];
    partial *= scale;

    // reduce over the 8 threads sharing the same output row i
    partial += __shfl_down_sync(0xffffffffu, partial, 4, 8);
    partial += __shfl_down_sync(0xffffffffu, partial, 2, 8);
    partial += __shfl_down_sync(0xffffffffu, partial, 1, 8);

    if ((tid & 7) == 0) atomicAdd(&g_hacc[u * SS + (tid >> 3)], partial);
    if (tid == 0)       atomicAdd(&g_cnt[u], 1);
}

// ---------------- output: H[v] = cnt*(hacc + R); out = log_softmax(H @ Wout + bout) ----------------
__global__ __launch_bounds__(256) void out_kernel(const float* __restrict__ Wout,
                                                  const float* __restrict__ bout,
                                                  float* __restrict__ out, int V) {
    int gtid = blockIdx.x * blockDim.x + threadIdx.x;
    int vtx = gtid >> 5;
    int lane = threadIdx.x & 31;
    if (vtx >= V) return;

    float hv = g_hacc[vtx * SS + lane];
    float rv = g_R[vtx * SS + lane];
    float c  = (float)g_cnt[vtx];
    float Hf = c * (hv + rv);

    float mine = 0.0f;
    float logits[CC];
#pragma unroll
    for (int j = 0; j < CC; ++j) {
        float p = Hf * Wout[lane * CC + j];
#pragma unroll
        for (int off = 16; off > 0; off >>= 1)
            p += __shfl_xor_sync(0xffffffffu, p, off);
        logits[j] = p + bout[j];
        if (j == lane) mine = logits[j];
    }
    float m = logits[0];
#pragma unroll
    for (int j = 1; j < CC; ++j) m = fmaxf(m, logits[j]);
    float se = 0.0f;
#pragma unroll
    for (int j = 0; j < CC; ++j) se += expf(logits[j] - m);
    float lse = m + logf(se);

    if (lane < CC) out[(size_t)vtx * CC + lane] = mine - lse;
}

// ---------------- launch ----------------
extern "C" void kernel_launch(void* const* d_in, const int* in_sizes, int n_in,
                              void* d_out, int out_size) {
    const float* feat = (const float*)d_in[0];
    const int*   Xn   = (const int*)d_in[1];
    const int*   Xe   = (const int*)d_in[2];
    const float* dg   = (const float*)d_in[3];
    const float* Wxi  = (const float*)d_in[4];
    const float* bxi  = (const float*)d_in[5];
    const float* Wrou = (const float*)d_in[6];
    const float* brou = (const float*)d_in[7];
    const float* Wout = (const float*)d_in[8];
    const float* bout = (const float*)d_in[9];
    float* out = (float*)d_out;

    const int V = in_sizes[0] / LNF;
    const int E = in_sizes[1];

    pack_w2_kernel<<<(LNF * NPQ + 255) / 256, 256>>>(Wxi);
    zero_kernel<<<(V * SS + 255) / 256, 256>>>(V);

    dim3 ggrid(NPQ / BN, (V + BM - 1) / BM);
    gemm_pq_kernel<<<ggrid, 256>>>(feat, V);

    r_kernel<<<(V + 7) / 8, 256>>>(feat, Wrou, brou, V);
    edge_kernel<<<E, 256>>>(Xn, Xe, dg, bxi, E);
    out_kernel<<<(V * 32 + 255) / 256, 256>>>(Wout, bout, out, V);
}

// round 2
// speedup vs baseline: 2.5327x; 2.5327x over previous
#include <cuda_runtime.h>
#include <cuda_fp16.h>
#include <math.h>
#include <stdint.h>

// Problem constants (fixed by dataset)
#define LNF 128      // feat dim
#define SS  32       // stat dim
#define CC  10       // classes
#define NPQ 2048     // P(1024) || Q(1024) per node
#define NTOT 2176    // GEMM N: 2048 PQ + 32 R cols + 96 pad (17 * 128)
#define MAXV 50000
#define MU_OVER_S (0.9f / 32.0f)

// -------- static device scratch --------
__device__ __half g_PQh[(size_t)MAXV * NPQ];   // ~205 MB fp16: P | Q (bxi pre-added into P)
__device__ float  g_W2[LNF * NTOT];            // [128 x 2176] = [Wxi_top | Wxi_bot | Wrou | 0]
__device__ float  g_R[MAXV * SS];              // R[v] = tanh(feat @ Wrou + brou)
__device__ float  g_hacc[MAXV * SS];           // sum_e A_e @ R[u_e]
__device__ int    g_cnt[MAXV];

__device__ __forceinline__ float fast_tanh(float x) {
    float y;
    asm("tanh.approx.f32 %0, %1;" : "=f"(y) : "f"(x));
    return y;
}

__device__ __forceinline__ void mma_tf32(float* c, const uint32_t* a, uint32_t b0, uint32_t b1) {
    asm volatile(
        "mma.sync.aligned.m16n8k8.row.col.f32.tf32.tf32.f32 "
        "{%0,%1,%2,%3}, {%4,%5,%6,%7}, {%8,%9}, {%0,%1,%2,%3};\n"
        : "+f"(c[0]), "+f"(c[1]), "+f"(c[2]), "+f"(c[3])
        : "r"(a[0]), "r"(a[1]), "r"(a[2]), "r"(a[3]), "r"(b0), "r"(b1));
}

// ---------------- pack W2 [128 x 2176] ----------------
__global__ void pack_w2_kernel(const float* __restrict__ Wxi, const float* __restrict__ Wrou) {
    int idx = blockIdx.x * blockDim.x + threadIdx.x;
    if (idx >= LNF * NTOT) return;
    int k = idx / NTOT, j = idx - k * NTOT;
    float v;
    if (j < 1024)       v = Wxi[k * 1024 + j];
    else if (j < 2048)  v = Wxi[(k + LNF) * 1024 + (j - 1024)];
    else if (j < 2080)  v = Wrou[k * SS + (j - 2048)];
    else                v = 0.0f;
    g_W2[idx] = v;
}

__global__ void zero_kernel(int V) {
    int idx = blockIdx.x * blockDim.x + threadIdx.x;
    if (idx < V * SS) g_hacc[idx] = 0.0f;
    if (idx < V)      g_cnt[idx]  = 0;
}

// ---------------- tf32 MMA GEMM: [M x 128] @ [128 x 2176] ----------------
// Block 128x128 tile, 8 warps as 4(M) x 2(N); warp = 32(M) x 64(N);
// per warp: 2 m-tiles (m16) x 8 n-tiles (n8), k-steps of 8.
#define GBM 128
#define GBN 128
#define GBK 32

__device__ __forceinline__ void epi_store(int row, int col, float v0, float v1, int M,
                                          const float* __restrict__ bxi,
                                          const float* __restrict__ brou) {
    if (row >= M) return;
    if (col < NPQ) {
        if (col < 1024) { v0 += __ldg(&bxi[col]); v1 += __ldg(&bxi[col + 1]); }
        *(__half2*)(g_PQh + (size_t)row * NPQ + col) = __floats2half2_rn(v0, v1);
    } else if (col < 2080) {
        int j = col - 2048;
        g_R[row * SS + j]     = tanhf(v0 + __ldg(&brou[j]));
        g_R[row * SS + j + 1] = tanhf(v1 + __ldg(&brou[j + 1]));
    }
}

__global__ __launch_bounds__(256) void gemm_mma_kernel(const float* __restrict__ A,
                                                       const float* __restrict__ bxi,
                                                       const float* __restrict__ brou, int M) {
    __shared__ float As[GBM][GBK + 4];    // stride 36: conflict-free frag reads
    __shared__ float Bs[GBK][GBN + 8];    // stride 136

    const int tid  = threadIdx.x;
    const int warp = tid >> 5;
    const int lane = tid & 31;
    const int g    = lane >> 2;
    const int t4   = lane & 3;
    const int wm   = warp & 3;       // 0..3 over M
    const int wn   = warp >> 2;      // 0..1 over N
    const int row0 = blockIdx.y * GBM;
    const int col0 = blockIdx.x * GBN;

    float acc[2][8][4];
#pragma unroll
    for (int mt = 0; mt < 2; ++mt)
#pragma unroll
        for (int nt = 0; nt < 8; ++nt)
#pragma unroll
            for (int r = 0; r < 4; ++r) acc[mt][nt][r] = 0.0f;

    for (int kt = 0; kt < LNF; kt += GBK) {
        // A tile: 128 rows x 32 k  (1024 float4, 4/thread)
#pragma unroll
        for (int i = 0; i < 4; ++i) {
            int lin = tid + i * 256;
            int r = lin >> 3;
            int kq = lin & 7;
            float4 v = make_float4(0.f, 0.f, 0.f, 0.f);
            if (row0 + r < M)
                v = *(const float4*)(A + (size_t)(row0 + r) * LNF + kt + kq * 4);
            *(float4*)&As[r][kq * 4] = v;
        }
        // B tile: 32 k x 128 n
#pragma unroll
        for (int i = 0; i < 4; ++i) {
            int lin = tid + i * 256;
            int r = lin >> 5;
            int cq = lin & 31;
            float4 v = *(const float4*)(g_W2 + (size_t)(kt + r) * NTOT + col0 + cq * 4);
            *(float4*)&Bs[r][cq * 4] = v;
        }
        __syncthreads();

#pragma unroll
        for (int kk = 0; kk < 4; ++kk) {
            const int kb = kk * 8;
            uint32_t afr[2][4];
#pragma unroll
            for (int mt = 0; mt < 2; ++mt) {
                int ar = wm * 32 + mt * 16;
                afr[mt][0] = __float_as_uint(As[ar + g][kb + t4]);
                afr[mt][1] = __float_as_uint(As[ar + g + 8][kb + t4]);
                afr[mt][2] = __float_as_uint(As[ar + g][kb + t4 + 4]);
                afr[mt][3] = __float_as_uint(As[ar + g + 8][kb + t4 + 4]);
            }
#pragma unroll
            for (int nt = 0; nt < 8; ++nt) {
                int bc = wn * 64 + nt * 8 + g;
                uint32_t b0 = __float_as_uint(Bs[kb + t4][bc]);
                uint32_t b1 = __float_as_uint(Bs[kb + t4 + 4][bc]);
#pragma unroll
                for (int mt = 0; mt < 2; ++mt)
                    mma_tf32(acc[mt][nt], afr[mt], b0, b1);
            }
        }
        __syncthreads();
    }

    // epilogue: C[g][2t4], C[g][2t4+1], C[g+8][2t4], C[g+8][2t4+1]
#pragma unroll
    for (int mt = 0; mt < 2; ++mt) {
        int rlo = row0 + wm * 32 + mt * 16 + g;
#pragma unroll
        for (int nt = 0; nt < 8; ++nt) {
            int c = col0 + wn * 64 + nt * 8 + 2 * t4;
            epi_store(rlo,     c, acc[mt][nt][0], acc[mt][nt][1], M, bxi, brou);
            epi_store(rlo + 8, c, acc[mt][nt][2], acc[mt][nt][3], M, bxi, brou);
        }
    }
}

// ---------------- edge kernel: warp per edge ----------------
// lane i: partial = sum_j tanh(P[u][i*32+j] + Q[v][i*32+j]) * R[u][j]; atomic into hacc[u][i]
__global__ __launch_bounds__(256) void edge_kernel(const int* __restrict__ Xn,
                                                   const int* __restrict__ Xe,
                                                   const float* __restrict__ dg, int E) {
    __shared__ float rs[8][33];
    const int warp = threadIdx.x >> 5;
    const int lane = threadIdx.x & 31;
    const int e = blockIdx.x * 8 + warp;
    if (e >= E) return;

    const int u = Xn[e];
    const int v = Xe[e];
    const float scale = MU_OVER_S / dg[e];

    rs[warp][lane] = g_R[u * SS + lane];
    __syncwarp();

    const uint4* Pp = (const uint4*)(g_PQh + (size_t)u * NPQ) + lane * 4;
    const uint4* Qp = (const uint4*)(g_PQh + (size_t)v * NPQ + 1024) + lane * 4;

    float partial = 0.0f;
#pragma unroll
    for (int q = 0; q < 4; ++q) {
        uint4 pu = Pp[q];
        uint4 qu = Qp[q];
        const __half2* ph = (const __half2*)&pu;
        const __half2* qh = (const __half2*)&qu;
#pragma unroll
        for (int k = 0; k < 4; ++k) {
            float2 pf = __half22float2(ph[k]);
            float2 qf = __half22float2(qh[k]);
            int j = q * 8 + k * 2;
            partial += fast_tanh(pf.x + qf.x) * rs[warp][j];
            partial += fast_tanh(pf.y + qf.y) * rs[warp][j + 1];
        }
    }

    atomicAdd(&g_hacc[u * SS + lane], partial * scale);
    if (lane == 0) atomicAdd(&g_cnt[u], 1);
}

// ---------------- output: H = cnt*(hacc + R); out = log_softmax(H @ Wout + bout) ----------------
__global__ __launch_bounds__(256) void out_kernel(const float* __restrict__ Wout,
                                                  const float* __restrict__ bout,
                                                  float* __restrict__ out, int V) {
    int gtid = blockIdx.x * blockDim.x + threadIdx.x;
    int vtx = gtid >> 5;
    int lane = threadIdx.x & 31;
    if (vtx >= V) return;

    float hv = g_hacc[vtx * SS + lane];
    float rv = g_R[vtx * SS + lane];
    float c  = (float)g_cnt[vtx];
    float Hf = c * (hv + rv);

    float mine = 0.0f;
    float logits[CC];
#pragma unroll
    for (int j = 0; j < CC; ++j) {
        float p = Hf * Wout[lane * CC + j];
#pragma unroll
        for (int off = 16; off > 0; off >>= 1)
            p += __shfl_xor_sync(0xffffffffu, p, off);
        logits[j] = p + bout[j];
        if (j == lane) mine = logits[j];
    }
    float m = logits[0];
#pragma unroll
    for (int j = 1; j < CC; ++j) m = fmaxf(m, logits[j]);
    float se = 0.0f;
#pragma unroll
    for (int j = 0; j < CC; ++j) se += expf(logits[j] - m);
    float lse = m + logf(se);

    if (lane < CC) out[(size_t)vtx * CC + lane] = mine - lse;
}

// ---------------- launch ----------------
extern "C" void kernel_launch(void* const* d_in, const int* in_sizes, int n_in,
                              void* d_out, int out_size) {
    const float* feat = (const float*)d_in[0];
    const int*   Xn   = (const int*)d_in[1];
    const int*   Xe   = (const int*)d_in[2];
    const float* dg   = (const float*)d_in[3];
    const float* Wxi  = (const float*)d_in[4];
    const float* bxi  = (const float*)d_in[5];
    const float* Wrou = (const float*)d_in[6];
    const float* brou = (const float*)d_in[7];
    const float* Wout = (const float*)d_in[8];
    const float* bout = (const float*)d_in[9];
    float* out = (float*)d_out;

    const int V = in_sizes[0] / LNF;
    const int E = in_sizes[1];

    pack_w2_kernel<<<(LNF * NTOT + 255) / 256, 256>>>(Wxi, Wrou);
    zero_kernel<<<(V * SS + 255) / 256, 256>>>(V);

    dim3 ggrid(NTOT / GBN, (V + GBM - 1) / GBM);   // x-inner => A-tile reuse in L2
    gemm_mma_kernel<<<ggrid, 256>>>(feat, bxi, brou, V);

    edge_kernel<<<(E + 7) / 8, 256>>>(Xn, Xe, dg, E);
    out_kernel<<<(V * 32 + 255) / 256, 256>>>(Wout, bout, out, V);
}

// round 4
// speedup vs baseline: 2.8803x; 1.1373x over previous
#include <cuda_runtime.h>
#include <cuda_fp16.h>
#include <cuda_bf16.h>
#include <math.h>
#include <stdint.h>

#define LNF 128      // feat dim
#define SS  32       // stat dim
#define CC  10       // classes
#define NPQ 2048     // P(1024) || Q(1024)
#define MAXV 50000
#define MAXE 200000
#define MU_OVER_S (0.9f / 32.0f)

// -------- static device scratch --------
__device__ __half         g_PQh[(size_t)MAXV * NPQ];  // fp16 P|Q (bxi folded into P)
__device__ __nv_bfloat16  g_W2b[LNF * NPQ];           // bf16 [128 x 2048] = [Wxi_top | Wxi_bot]
__device__ __nv_bfloat16  g_fb[(size_t)MAXV * LNF];   // bf16 feat
__device__ float          g_R[MAXV * SS];             // fp32 R = tanh(feat@Wrou + brou)
__device__ float          g_hacc[MAXV * SS];
__device__ int            g_cnt[MAXV];
__device__ int            g_fill[MAXV];
__device__ int            g_off[MAXV + 1];
__device__ int            g_ev[MAXE];                 // CSR: neighbor v per slot
__device__ float          g_esc[MAXE];                // CSR: per-edge scale

__device__ __forceinline__ float fast_tanh(float x) {
    float y;
    asm("tanh.approx.f32 %0, %1;" : "=f"(y) : "f"(x));
    return y;
}

// ---------------- packing / conversion ----------------
__global__ void pack_w2_kernel(const float* __restrict__ Wxi) {
    int idx = blockIdx.x * blockDim.x + threadIdx.x;
    if (idx >= LNF * NPQ) return;
    int k = idx / NPQ, j = idx - k * NPQ;
    float v = (j < 1024) ? Wxi[k * 1024 + j] : Wxi[(k + LNF) * 1024 + (j - 1024)];
    g_W2b[idx] = __float2bfloat16(v);
}

__global__ void cvt_feat_kernel(const float* __restrict__ feat, int n) {
    int idx = blockIdx.x * blockDim.x + threadIdx.x;   // over float2 pairs
    if (idx * 2 >= n) return;
    float2 f = ((const float2*)feat)[idx];
    ((__nv_bfloat162*)g_fb)[idx] = __floats2bfloat162_rn(f.x, f.y);
}

__global__ void zero_kernel(int V) {
    int idx = blockIdx.x * blockDim.x + threadIdx.x;
    if (idx < V) { g_cnt[idx] = 0; g_fill[idx] = 0; }
}

// ---------------- CSR build ----------------
__global__ void count_kernel(const int* __restrict__ Xn, int E) {
    int e = blockIdx.x * blockDim.x + threadIdx.x;
    if (e < E) atomicAdd(&g_cnt[Xn[e]], 1);
}

__global__ __launch_bounds__(1024) void scan_kernel(int V) {
    __shared__ int s[1024];
    const int tid = threadIdx.x;
    const int chunk = (V + 1023) / 1024;
    int lo = tid * chunk;
    int hi = lo + chunk; if (hi > V) hi = V; if (lo > V) lo = V;
    int sum = 0;
    for (int i = lo; i < hi; ++i) sum += g_cnt[i];
    s[tid] = sum;
    __syncthreads();
    for (int off = 1; off < 1024; off <<= 1) {
        int v = 0;
        if (tid >= off) v = s[tid - off];
        __syncthreads();
        if (tid >= off) s[tid] += v;
        __syncthreads();
    }
    int run = (tid > 0) ? s[tid - 1] : 0;
    for (int i = lo; i < hi; ++i) { g_off[i] = run; run += g_cnt[i]; }
    if (tid == 1023) g_off[V] = s[1023];
}

__global__ void fill_kernel(const int* __restrict__ Xn, const int* __restrict__ Xe,
                            const float* __restrict__ dg, int E) {
    int e = blockIdx.x * blockDim.x + threadIdx.x;
    if (e >= E) return;
    int u = Xn[e];
    int pos = g_off[u] + atomicAdd(&g_fill[u], 1);
    g_ev[pos]  = Xe[e];
    g_esc[pos] = MU_OVER_S / dg[e];
}

// ---------------- bf16 MMA GEMM: PQ[M x 2048] = featbf[M x 128] @ W2b ----------------
// 128x128 block tile, full K=128 staged once via cp.async. 8 warps = 4(M) x 2(N).
#define AS_STRIDE 136   // halves; 272B row stride => ldmatrix conflict-free
#define SMEM_B_OFF (128 * AS_STRIDE)       // in bf16 elements
#define GEMM_SMEM_BYTES (2 * 128 * AS_STRIDE * 2)

__device__ __forceinline__ void ldsm_x4(uint32_t& r0, uint32_t& r1, uint32_t& r2, uint32_t& r3,
                                        uint32_t addr) {
    asm volatile("ldmatrix.sync.aligned.m8n8.x4.shared.b16 {%0,%1,%2,%3}, [%4];"
                 : "=r"(r0), "=r"(r1), "=r"(r2), "=r"(r3) : "r"(addr));
}
__device__ __forceinline__ void ldsm_x4_t(uint32_t& r0, uint32_t& r1, uint32_t& r2, uint32_t& r3,
                                          uint32_t addr) {
    asm volatile("ldmatrix.sync.aligned.m8n8.x4.trans.shared.b16 {%0,%1,%2,%3}, [%4];"
                 : "=r"(r0), "=r"(r1), "=r"(r2), "=r"(r3) : "r"(addr));
}
__device__ __forceinline__ void mma_bf16(float* c, const uint32_t* a, uint32_t b0, uint32_t b1) {
    asm volatile(
        "mma.sync.aligned.m16n8k16.row.col.f32.bf16.bf16.f32 "
        "{%0,%1,%2,%3}, {%4,%5,%6,%7}, {%8,%9}, {%0,%1,%2,%3};\n"
        : "+f"(c[0]), "+f"(c[1]), "+f"(c[2]), "+f"(c[3])
        : "r"(a[0]), "r"(a[1]), "r"(a[2]), "r"(a[3]), "r"(b0), "r"(b1));
}
__device__ __forceinline__ void cp_async16(uint32_t saddr, const void* gaddr) {
    asm volatile("cp.async.cg.shared.global [%0], [%1], 16;" :: "r"(saddr), "l"(gaddr));
}

__global__ __launch_bounds__(256) void gemm_bf16_kernel(const float* __restrict__ bxi, int M) {
    extern __shared__ __nv_bfloat16 smem[];

    const int tid  = threadIdx.x;
    const int warp = tid >> 5;
    const int lane = tid & 31;
    const int g    = lane >> 2;
    const int t4   = lane & 3;
    const int wm   = warp & 3;
    const int wn   = warp >> 2;
    const int row0 = blockIdx.y * 128;
    const int col0 = blockIdx.x * 128;

    uint32_t smem_base;
    asm("{ .reg .u64 t; cvta.to.shared.u64 t, %1; cvt.u32.u64 %0, t; }"
        : "=r"(smem_base) : "l"(smem));

    // Stage A and B tiles. Each is 128 rows x 16 chunks of 16B (= 128 bf16/row).
    // 2048 chunks each, 8 per thread: r = c>>4 (0..127), seg = c&15 (0..15).
#pragma unroll
    for (int i = 0; i < 8; ++i) {
        int c = tid + i * 256;
        int r = c >> 4;                 // row 0..127
        int seg = c & 15;               // 16B segment 0..15
        int grow = row0 + r; if (grow >= M) grow = M - 1;
        cp_async16(smem_base + (uint32_t)(r * AS_STRIDE + seg * 8) * 2,
                   g_fb + (size_t)grow * LNF + seg * 8);                       // A[r][k]
        cp_async16(smem_base + (uint32_t)(SMEM_B_OFF + r * AS_STRIDE + seg * 8) * 2,
                   g_W2b + (size_t)r * NPQ + col0 + seg * 8);                  // B[k][n]
    }
    asm volatile("cp.async.commit_group;");
    asm volatile("cp.async.wait_group 0;");
    __syncthreads();

    float acc[2][8][4];
#pragma unroll
    for (int mt = 0; mt < 2; ++mt)
#pragma unroll
        for (int nt = 0; nt < 8; ++nt)
#pragma unroll
            for (int r = 0; r < 4; ++r) acc[mt][nt][r] = 0.0f;

#pragma unroll
    for (int ks = 0; ks < 8; ++ks) {
        const int kb = ks * 16;
        uint32_t a[2][4];
#pragma unroll
        for (int mt = 0; mt < 2; ++mt) {
            int ar = wm * 32 + mt * 16;
            uint32_t addr = smem_base +
                (uint32_t)((ar + (lane & 15)) * AS_STRIDE + kb + ((lane >> 4) << 3)) * 2;
            ldsm_x4(a[mt][0], a[mt][1], a[mt][2], a[mt][3], addr);
        }
#pragma unroll
        for (int np = 0; np < 4; ++np) {          // pair of n8 tiles
            int nc = wn * 64 + np * 16;
            uint32_t b0, b1, b2, b3;
            uint32_t addr = smem_base +
                (uint32_t)(SMEM_B_OFF + (kb + (lane & 15)) * AS_STRIDE + nc + ((lane >> 4) << 3)) * 2;
            ldsm_x4_t(b0, b1, b2, b3, addr);
#pragma unroll
            for (int mt = 0; mt < 2; ++mt) {
                mma_bf16(acc[mt][np * 2],     a[mt], b0, b1);
                mma_bf16(acc[mt][np * 2 + 1], a[mt], b2, b3);
            }
        }
    }

    // epilogue: add bxi (cols < 1024), store fp16
#pragma unroll
    for (int mt = 0; mt < 2; ++mt) {
        int rlo = row0 + wm * 32 + mt * 16 + g;
#pragma unroll
        for (int nt = 0; nt < 8; ++nt) {
            int c = col0 + wn * 64 + nt * 8 + 2 * t4;
            float b0 = 0.f, b1 = 0.f;
            if (c < 1024) { b0 = __ldg(&bxi[c]); b1 = __ldg(&bxi[c + 1]); }
            if (rlo < M)
                *(__half2*)(g_PQh + (size_t)rlo * NPQ + c) =
                    __floats2half2_rn(acc[mt][nt][0] + b0, acc[mt][nt][1] + b1);
            if (rlo + 8 < M)
                *(__half2*)(g_PQh + (size_t)(rlo + 8) * NPQ + c) =
                    __floats2half2_rn(acc[mt][nt][2] + b0, acc[mt][nt][3] + b1);
        }
    }
}

// ---------------- R kernel: full fp32, 48 nodes/block, 6 nodes/thread ----------------
#define RNODES 48
__global__ __launch_bounds__(256) void r_kernel(const float* __restrict__ feat,
                                                const float* __restrict__ Wrou,
                                                const float* __restrict__ brou, int V) {
    __shared__ float Ws[LNF * SS];          // 16 KB
    __shared__ float fr[RNODES * LNF];      // 24 KB
    const int tid = threadIdx.x;
    const int n0 = blockIdx.x * RNODES;

    for (int i = tid; i < LNF * SS; i += 256) Ws[i] = Wrou[i];
    for (int i = tid; i < RNODES * LNF / 4; i += 256) {
        int node = n0 + (i * 4) / LNF;
        if (node >= V) node = V - 1;
        int k = (i * 4) & (LNF - 1);
        *(float4*)&fr[i * 4] = *(const float4*)(feat + (size_t)node * LNF + k);
    }
    __syncthreads();

    const int warp = tid >> 5, lane = tid & 31;
    float acc[6];
#pragma unroll
    for (int i = 0; i < 6; ++i) acc[i] = 0.0f;
    const float* fbase = &fr[warp * 6 * LNF];
#pragma unroll 16
    for (int k = 0; k < LNF; ++k) {
        float wv = Ws[k * SS + lane];
#pragma unroll
        for (int i = 0; i < 6; ++i) acc[i] = fmaf(fbase[i * LNF + k], wv, acc[i]);
    }
    float bb = brou[lane];
#pragma unroll
    for (int i = 0; i < 6; ++i) {
        int node = n0 + warp * 6 + i;
        if (node < V) g_R[node * SS + lane] = tanhf(acc[i] + bb);
    }
}

// ---------------- edge kernel: one warp per node (CSR) ----------------
__global__ __launch_bounds__(256) void edge2_kernel(int V) {
    __shared__ float rs[8][SS];
    const int warp = threadIdx.x >> 5;
    const int lane = threadIdx.x & 31;
    const int u = blockIdx.x * 8 + warp;
    if (u >= V) return;
    const int n = g_cnt[u];
    if (n == 0) return;
    const int start = g_off[u];

    rs[warp][lane] = g_R[u * SS + lane];
    __syncwarp();

    // P row (bxi folded): lane covers elements [lane*32, lane*32+32)
    const uint4* Pp = (const uint4*)(g_PQh + (size_t)u * NPQ) + lane * 4;
    uint4 pr[4] = {Pp[0], Pp[1], Pp[2], Pp[3]};

    float acc = 0.0f;
    for (int e = start; e < start + n; ++e) {
        const int v = g_ev[e];
        const float sc = g_esc[e];
        const uint4* Qp = (const uint4*)(g_PQh + (size_t)v * NPQ + 1024) + lane * 4;
        float partial = 0.0f;
#pragma unroll
        for (int q = 0; q < 4; ++q) {
            uint4 qv = Qp[q];
            const __half2* ph = (const __half2*)&pr[q];
            const __half2* qh = (const __half2*)&qv;
#pragma unroll
            for (int k = 0; k < 4; ++k) {
                float2 f = __half22float2(__hadd2(ph[k], qh[k]));
                int j = q * 8 + k * 2;
                partial += fast_tanh(f.x) * rs[warp][j];
                partial += fast_tanh(f.y) * rs[warp][j + 1];
            }
        }
        acc = fmaf(partial, sc, acc);
    }
    g_hacc[u * SS + lane] = acc;
}

// ---------------- output ----------------
__global__ __launch_bounds__(256) void out_kernel(const float* __restrict__ Wout,
                                                  const float* __restrict__ bout,
                                                  float* __restrict__ out, int V) {
    int gtid = blockIdx.x * blockDim.x + threadIdx.x;
    int vtx = gtid >> 5;
    int lane = threadIdx.x & 31;
    if (vtx >= V) return;

    float c = (float)g_cnt[vtx];
    float Hf = (c > 0.0f) ? c * (g_hacc[vtx * SS + lane] + g_R[vtx * SS + lane]) : 0.0f;

    float mine = 0.0f;
    float logits[CC];
#pragma unroll
    for (int j = 0; j < CC; ++j) {
        float p = Hf * Wout[lane * CC + j];
#pragma unroll
        for (int off = 16; off > 0; off >>= 1)
            p += __shfl_xor_sync(0xffffffffu, p, off);
        logits[j] = p + bout[j];
        if (j == lane) mine = logits[j];
    }
    float m = logits[0];
#pragma unroll
    for (int j = 1; j < CC; ++j) m = fmaxf(m, logits[j]);
    float se = 0.0f;
#pragma unroll
    for (int j = 0; j < CC; ++j) se += expf(logits[j] - m);
    float lse = m + logf(se);

    if (lane < CC) out[(size_t)vtx * CC + lane] = mine - lse;
}

// ---------------- launch ----------------
extern "C" void kernel_launch(void* const* d_in, const int* in_sizes, int n_in,
                              void* d_out, int out_size) {
    const float* feat = (const float*)d_in[0];
    const int*   Xn   = (const int*)d_in[1];
    const int*   Xe   = (const int*)d_in[2];
    const float* dg   = (const float*)d_in[3];
    const float* Wxi  = (const float*)d_in[4];
    const float* bxi  = (const float*)d_in[5];
    const float* Wrou = (const float*)d_in[6];
    const float* brou = (const float*)d_in[7];
    const float* Wout = (const float*)d_in[8];
    const float* bout = (const float*)d_in[9];
    float* out = (float*)d_out;

    const int V = in_sizes[0] / LNF;
    const int E = in_sizes[1];

    cudaFuncSetAttribute(gemm_bf16_kernel,
                         cudaFuncAttributeMaxDynamicSharedMemorySize, GEMM_SMEM_BYTES);

    pack_w2_kernel<<<(LNF * NPQ + 255) / 256, 256>>>(Wxi);
    cvt_feat_kernel<<<(V * LNF / 2 + 255) / 256, 256>>>(feat, V * LNF);
    zero_kernel<<<(V + 255) / 256, 256>>>(V);
    count_kernel<<<(E + 255) / 256, 256>>>(Xn, E);
    scan_kernel<<<1, 1024>>>(V);
    fill_kernel<<<(E + 255) / 256, 256>>>(Xn, Xe, dg, E);

    dim3 ggrid(NPQ / 128, (V + 127) / 128);
    gemm_bf16_kernel<<<ggrid, 256, GEMM_SMEM_BYTES>>>(bxi, V);

    r_kernel<<<(V + RNODES - 1) / RNODES, 256>>>(feat, Wrou, brou, V);
    edge2_kernel<<<(V + 7) / 8, 256>>>(V);
    out_kernel<<<(V * 32 + 255) / 256, 256>>>(Wout, bout, out, V);
}

// round 5
// speedup vs baseline: 3.2819x; 1.1394x over previous
#include <cuda_runtime.h>
#include <cuda_fp16.h>
#include <cuda_bf16.h>
#include <math.h>
#include <stdint.h>

#define LNF 128      // feat dim
#define SS  32       // stat dim
#define CC  10       // classes
#define NPQ 2048     // P(1024) || Q(1024)
#define MAXV 50000
#define MAXE 200000
#define MU_OVER_S (0.9f / 32.0f)

// -------- static device scratch --------
__device__ __half         g_PQh[(size_t)MAXV * NPQ];  // fp16 P|Q (bxi folded into P)
__device__ __nv_bfloat16  g_W2b[LNF * NPQ];           // bf16 [128 x 2048] = [Wxi_top | Wxi_bot]
__device__ __nv_bfloat16  g_fb[(size_t)MAXV * LNF];   // bf16 feat
__device__ float          g_R[MAXV * SS];             // fp32 R = tanh(feat@Wrou + brou)
__device__ float          g_hacc[MAXV * SS];
__device__ int            g_cnt[MAXV];
__device__ int            g_fill[MAXV];
__device__ int            g_off[MAXV + 1];
__device__ int            g_ev[MAXE];                 // CSR: neighbor v per slot
__device__ float          g_esc[MAXE];                // CSR: per-edge scale

__device__ __forceinline__ float fast_tanh(float x) {
    float y;
    asm("tanh.approx.f32 %0, %1;" : "=f"(y) : "f"(x));
    return y;
}

// ---------------- packing ----------------
__global__ void pack_w2_kernel(const float* __restrict__ Wxi) {
    int idx = blockIdx.x * blockDim.x + threadIdx.x;
    if (idx >= LNF * NPQ) return;
    int k = idx / NPQ, j = idx - k * NPQ;
    float v = (j < 1024) ? Wxi[k * 1024 + j] : Wxi[(k + LNF) * 1024 + (j - 1024)];
    g_W2b[idx] = __float2bfloat16(v);
}

__global__ void zero_kernel(int V) {
    int idx = blockIdx.x * blockDim.x + threadIdx.x;
    if (idx < V) { g_cnt[idx] = 0; g_fill[idx] = 0; }
}

// ---------------- CSR build ----------------
__global__ void count_kernel(const int* __restrict__ Xn, int E) {
    int e = blockIdx.x * blockDim.x + threadIdx.x;
    if (e < E) atomicAdd(&g_cnt[Xn[e]], 1);
}

__global__ __launch_bounds__(1024) void scan_kernel(int V) {
    __shared__ int s[1024];
    const int tid = threadIdx.x;
    const int chunk = (V + 1023) / 1024;
    int lo = tid * chunk;
    int hi = lo + chunk; if (hi > V) hi = V; if (lo > V) lo = V;
    int sum = 0;
    for (int i = lo; i < hi; ++i) sum += g_cnt[i];
    s[tid] = sum;
    __syncthreads();
    for (int off = 1; off < 1024; off <<= 1) {
        int v = 0;
        if (tid >= off) v = s[tid - off];
        __syncthreads();
        if (tid >= off) s[tid] += v;
        __syncthreads();
    }
    int run = (tid > 0) ? s[tid - 1] : 0;
    for (int i = lo; i < hi; ++i) { g_off[i] = run; run += g_cnt[i]; }
    if (tid == 1023) g_off[V] = s[1023];
}

__global__ void fill_kernel(const int* __restrict__ Xn, const int* __restrict__ Xe,
                            const float* __restrict__ dg, int E) {
    int e = blockIdx.x * blockDim.x + threadIdx.x;
    if (e >= E) return;
    int u = Xn[e];
    int pos = g_off[u] + atomicAdd(&g_fill[u], 1);
    g_ev[pos]  = Xe[e];
    g_esc[pos] = MU_OVER_S / dg[e];
}

// ---------------- bf16 MMA GEMM: PQ[M x 2048] = featbf[M x 128] @ W2b ----------------
#define AS_STRIDE 136   // halves; 272B row stride => ldmatrix conflict-free
#define SMEM_B_OFF (128 * AS_STRIDE)
#define GEMM_SMEM_BYTES (2 * 128 * AS_STRIDE * 2)

__device__ __forceinline__ void ldsm_x4(uint32_t& r0, uint32_t& r1, uint32_t& r2, uint32_t& r3,
                                        uint32_t addr) {
    asm volatile("ldmatrix.sync.aligned.m8n8.x4.shared.b16 {%0,%1,%2,%3}, [%4];"
                 : "=r"(r0), "=r"(r1), "=r"(r2), "=r"(r3) : "r"(addr));
}
__device__ __forceinline__ void ldsm_x4_t(uint32_t& r0, uint32_t& r1, uint32_t& r2, uint32_t& r3,
                                          uint32_t addr) {
    asm volatile("ldmatrix.sync.aligned.m8n8.x4.trans.shared.b16 {%0,%1,%2,%3}, [%4];"
                 : "=r"(r0), "=r"(r1), "=r"(r2), "=r"(r3) : "r"(addr));
}
__device__ __forceinline__ void mma_bf16(float* c, const uint32_t* a, uint32_t b0, uint32_t b1) {
    asm volatile(
        "mma.sync.aligned.m16n8k16.row.col.f32.bf16.bf16.f32 "
        "{%0,%1,%2,%3}, {%4,%5,%6,%7}, {%8,%9}, {%0,%1,%2,%3};\n"
        : "+f"(c[0]), "+f"(c[1]), "+f"(c[2]), "+f"(c[3])
        : "r"(a[0]), "r"(a[1]), "r"(a[2]), "r"(a[3]), "r"(b0), "r"(b1));
}
__device__ __forceinline__ void cp_async16(uint32_t saddr, const void* gaddr) {
    asm volatile("cp.async.cg.shared.global [%0], [%1], 16;" :: "r"(saddr), "l"(gaddr));
}

__global__ __launch_bounds__(256) void gemm_bf16_kernel(const float* __restrict__ bxi, int M) {
    extern __shared__ __nv_bfloat16 smem[];

    const int tid  = threadIdx.x;
    const int warp = tid >> 5;
    const int lane = tid & 31;
    const int g    = lane >> 2;
    const int t4   = lane & 3;
    const int wm   = warp & 3;
    const int wn   = warp >> 2;
    const int row0 = blockIdx.y * 128;
    const int col0 = blockIdx.x * 128;

    uint32_t smem_base;
    asm("{ .reg .u64 t; cvta.to.shared.u64 t, %1; cvt.u32.u64 %0, t; }"
        : "=r"(smem_base) : "l"(smem));

    // Stage A and B tiles: each 128 rows x 16 segs of 16B; 8 chunks/thread each.
#pragma unroll
    for (int i = 0; i < 8; ++i) {
        int c = tid + i * 256;
        int r = c >> 4;
        int seg = c & 15;
        int grow = row0 + r; if (grow >= M) grow = M - 1;
        cp_async16(smem_base + (uint32_t)(r * AS_STRIDE + seg * 8) * 2,
                   g_fb + (size_t)grow * LNF + seg * 8);
        cp_async16(smem_base + (uint32_t)(SMEM_B_OFF + r * AS_STRIDE + seg * 8) * 2,
                   g_W2b + (size_t)r * NPQ + col0 + seg * 8);
    }
    asm volatile("cp.async.commit_group;");
    asm volatile("cp.async.wait_group 0;");
    __syncthreads();

    float acc[2][8][4];
#pragma unroll
    for (int mt = 0; mt < 2; ++mt)
#pragma unroll
        for (int nt = 0; nt < 8; ++nt)
#pragma unroll
            for (int r = 0; r < 4; ++r) acc[mt][nt][r] = 0.0f;

#pragma unroll
    for (int ks = 0; ks < 8; ++ks) {
        const int kb = ks * 16;
        uint32_t a[2][4];
#pragma unroll
        for (int mt = 0; mt < 2; ++mt) {
            int ar = wm * 32 + mt * 16;
            uint32_t addr = smem_base +
                (uint32_t)((ar + (lane & 15)) * AS_STRIDE + kb + ((lane >> 4) << 3)) * 2;
            ldsm_x4(a[mt][0], a[mt][1], a[mt][2], a[mt][3], addr);
        }
#pragma unroll
        for (int np = 0; np < 4; ++np) {
            int nc = wn * 64 + np * 16;
            uint32_t b0, b1, b2, b3;
            uint32_t addr = smem_base +
                (uint32_t)(SMEM_B_OFF + (kb + (lane & 15)) * AS_STRIDE + nc + ((lane >> 4) << 3)) * 2;
            ldsm_x4_t(b0, b1, b2, b3, addr);
#pragma unroll
            for (int mt = 0; mt < 2; ++mt) {
                mma_bf16(acc[mt][np * 2],     a[mt], b0, b1);
                mma_bf16(acc[mt][np * 2 + 1], a[mt], b2, b3);
            }
        }
    }

    // epilogue: add bxi (cols < 1024), streaming-store fp16
#pragma unroll
    for (int mt = 0; mt < 2; ++mt) {
        int rlo = row0 + wm * 32 + mt * 16 + g;
#pragma unroll
        for (int nt = 0; nt < 8; ++nt) {
            int c = col0 + wn * 64 + nt * 8 + 2 * t4;
            float b0 = 0.f, b1 = 0.f;
            if (c < 1024) { b0 = __ldg(&bxi[c]); b1 = __ldg(&bxi[c + 1]); }
            if (rlo < M)
                __stcs((__half2*)(g_PQh + (size_t)rlo * NPQ + c),
                       __floats2half2_rn(acc[mt][nt][0] + b0, acc[mt][nt][1] + b1));
            if (rlo + 8 < M)
                __stcs((__half2*)(g_PQh + (size_t)(rlo + 8) * NPQ + c),
                       __floats2half2_rn(acc[mt][nt][2] + b0, acc[mt][nt][3] + b1));
        }
    }
}

// ---------------- R kernel (fp32) + fused feat->bf16 conversion ----------------
#define RNODES 48
__global__ __launch_bounds__(256) void r_kernel(const float* __restrict__ feat,
                                                const float* __restrict__ Wrou,
                                                const float* __restrict__ brou, int V) {
    __shared__ float Ws[LNF * SS];          // 16 KB
    __shared__ float fr[RNODES * LNF];      // 24 KB
    const int tid = threadIdx.x;
    const int n0 = blockIdx.x * RNODES;

    for (int i = tid; i < LNF * SS; i += 256) Ws[i] = Wrou[i];
    for (int i = tid; i < RNODES * LNF / 4; i += 256) {
        int node = n0 + (i * 4) / LNF;
        if (node >= V) node = V - 1;
        int k = (i * 4) & (LNF - 1);
        *(float4*)&fr[i * 4] = *(const float4*)(feat + (size_t)node * LNF + k);
    }
    __syncthreads();

    // fused bf16 conversion (g_fb feeds the GEMM)
    for (int i = tid; i < RNODES * LNF / 2; i += 256) {
        int node = n0 + (i * 2) / LNF;
        if (node < V) {
            int k = (i * 2) & (LNF - 1);
            ((__nv_bfloat162*)(g_fb + (size_t)node * LNF + k))[0] =
                __floats2bfloat162_rn(fr[i * 2], fr[i * 2 + 1]);
        }
    }

    const int warp = tid >> 5, lane = tid & 31;
    float acc[6];
#pragma unroll
    for (int i = 0; i < 6; ++i) acc[i] = 0.0f;
    const float* fbase = &fr[warp * 6 * LNF];
#pragma unroll 16
    for (int k = 0; k < LNF; ++k) {
        float wv = Ws[k * SS + lane];
#pragma unroll
        for (int i = 0; i < 6; ++i) acc[i] = fmaf(fbase[i * LNF + k], wv, acc[i]);
    }
    float bb = brou[lane];
#pragma unroll
    for (int i = 0; i < 6; ++i) {
        int node = n0 + warp * 6 + i;
        if (node < V) g_R[node * SS + lane] = tanhf(acc[i] + bb);
    }
}

// ---------------- edge kernel: one warp per node, HALF of the S-rows per pass ----------------
// Pass p covers output rows i in [p*16, p*16+16) => PQ elements [p*512, p*512+512).
// Lane l: row i = p*16 + (l>>1), j-range = [(l&1)*16, (l&1)*16+16). 16 fp16 = 2x uint4.
// Q-half working set = 51 MB -> L2-resident; P-half streamed with evict-first.
__global__ __launch_bounds__(256) void edge_half_kernel(int V, int pass) {
    __shared__ float rs[8][SS];
    const int warp = threadIdx.x >> 5;
    const int lane = threadIdx.x & 31;
    const int u = blockIdx.x * 8 + warp;
    if (u >= V) return;
    const int n = g_cnt[u];
    if (n == 0) return;
    const int start = g_off[u];

    rs[warp][lane] = g_R[u * SS + lane];
    __syncwarp();

    const int row = lane >> 1;            // 0..15 (local)
    const int jh  = (lane & 1) * 16;      // j offset 0 or 16
    const size_t eoff = (size_t)pass * 512 + row * 32 + jh;

    const uint4 pA = __ldcs((const uint4*)(g_PQh + (size_t)u * NPQ + eoff));
    const uint4 pB = __ldcs((const uint4*)(g_PQh + (size_t)u * NPQ + eoff + 8));

    float racc = 0.0f;
    for (int e = start; e < start + n; ++e) {
        const int v = __ldcs(&g_ev[e]);
        const float sc = __ldcs(&g_esc[e]);
        const __half* qrow = g_PQh + (size_t)v * NPQ + 1024 + eoff;
        uint4 qA = *(const uint4*)qrow;
        uint4 qB = *(const uint4*)(qrow + 8);

        float partial = 0.0f;
        const __half2* ph;
        const __half2* qh;
        ph = (const __half2*)&pA; qh = (const __half2*)&qA;
#pragma unroll
        for (int k = 0; k < 4; ++k) {
            float2 f = __half22float2(__hadd2(ph[k], qh[k]));
            partial += fast_tanh(f.x) * rs[warp][jh + 2 * k];
            partial += fast_tanh(f.y) * rs[warp][jh + 2 * k + 1];
        }
        ph = (const __half2*)&pB; qh = (const __half2*)&qB;
#pragma unroll
        for (int k = 0; k < 4; ++k) {
            float2 f = __half22float2(__hadd2(ph[k], qh[k]));
            partial += fast_tanh(f.x) * rs[warp][jh + 8 + 2 * k];
            partial += fast_tanh(f.y) * rs[warp][jh + 8 + 2 * k + 1];
        }
        racc = fmaf(partial, sc, racc);
    }

    // combine the two j-halves (lane pairs)
    racc += __shfl_down_sync(0xffffffffu, racc, 1, 2);
    if ((lane & 1) == 0)
        g_hacc[u * SS + pass * 16 + row] = racc;
}

// ---------------- output ----------------
__global__ __launch_bounds__(256) void out_kernel(const float* __restrict__ Wout,
                                                  const float* __restrict__ bout,
                                                  float* __restrict__ out, int V) {
    int gtid = blockIdx.x * blockDim.x + threadIdx.x;
    int vtx = gtid >> 5;
    int lane = threadIdx.x & 31;
    if (vtx >= V) return;

    float c = (float)g_cnt[vtx];
    float Hf = (c > 0.0f) ? c * (g_hacc[vtx * SS + lane] + g_R[vtx * SS + lane]) : 0.0f;

    float mine = 0.0f;
    float logits[CC];
#pragma unroll
    for (int j = 0; j < CC; ++j) {
        float p = Hf * Wout[lane * CC + j];
#pragma unroll
        for (int off = 16; off > 0; off >>= 1)
            p += __shfl_xor_sync(0xffffffffu, p, off);
        logits[j] = p + bout[j];
        if (j == lane) mine = logits[j];
    }
    float m = logits[0];
#pragma unroll
    for (int j = 1; j < CC; ++j) m = fmaxf(m, logits[j]);
    float se = 0.0f;
#pragma unroll
    for (int j = 0; j < CC; ++j) se += expf(logits[j] - m);
    float lse = m + logf(se);

    if (lane < CC) out[(size_t)vtx * CC + lane] = mine - lse;
}

// ---------------- launch ----------------
extern "C" void kernel_launch(void* const* d_in, const int* in_sizes, int n_in,
                              void* d_out, int out_size) {
    const float* feat = (const float*)d_in[0];
    const int*   Xn   = (const int*)d_in[1];
    const int*   Xe   = (const int*)d_in[2];
    const float* dg   = (const float*)d_in[3];
    const float* Wxi  = (const float*)d_in[4];
    const float* bxi  = (const float*)d_in[5];
    const float* Wrou = (const float*)d_in[6];
    const float* brou = (const float*)d_in[7];
    const float* Wout = (const float*)d_in[8];
    const float* bout = (const float*)d_in[9];
    float* out = (float*)d_out;

    const int V = in_sizes[0] / LNF;
    const int E = in_sizes[1];

    cudaFuncSetAttribute(gemm_bf16_kernel,
                         cudaFuncAttributeMaxDynamicSharedMemorySize, GEMM_SMEM_BYTES);

    pack_w2_kernel<<<(LNF * NPQ + 255) / 256, 256>>>(Wxi);
    zero_kernel<<<(V + 255) / 256, 256>>>(V);
    count_kernel<<<(E + 255) / 256, 256>>>(Xn, E);
    scan_kernel<<<1, 1024>>>(V);
    fill_kernel<<<(E + 255) / 256, 256>>>(Xn, Xe, dg, E);

    r_kernel<<<(V + RNODES - 1) / RNODES, 256>>>(feat, Wrou, brou, V);   // also writes g_fb

    dim3 ggrid(NPQ / 128, (V + 127) / 128);
    gemm_bf16_kernel<<<ggrid, 256, GEMM_SMEM_BYTES>>>(bxi, V);

    edge_half_kernel<<<(V + 7) / 8, 256>>>(V, 0);
    edge_half_kernel<<<(V + 7) / 8, 256>>>(V, 1);
    out_kernel<<<(V * 32 + 255) / 256, 256>>>(Wout, bout, out, V);
}

// round 7
// speedup vs baseline: 3.5476x; 1.0810x over previous
#include <cuda_runtime.h>
#include <cuda_fp16.h>
#include <cuda_bf16.h>
#include <math.h>
#include <stdint.h>

#define LNF 128      // feat dim
#define SS  32       // stat dim
#define CC  10       // classes
#define NPQ 2048     // P(1024) || Q(1024)
#define MAXV 50000
#define MAXE 200000
#define MU_OVER_S (0.9f / 32.0f)
#define SCAN_BLK 512
#define MAXB ((MAXV + SCAN_BLK - 1) / SCAN_BLK)   // 98

// -------- static device scratch --------
__device__ __half         g_PQh[(size_t)MAXV * NPQ];  // fp16 P|Q (bxi folded into P)
__device__ __nv_bfloat16  g_W2b[LNF * NPQ];           // bf16 [128 x 2048]
__device__ __nv_bfloat16  g_fb[(size_t)MAXV * LNF];   // bf16 feat
__device__ float          g_R[MAXV * SS];             // fp32 R
__device__ float          g_hacc[MAXV * SS];
__device__ int            g_cnt[MAXV];
__device__ int            g_fill[MAXV];
__device__ int            g_off[MAXV + 1];
__device__ int            g_bsum[MAXB];
__device__ int            g_ev[MAXE];
__device__ float          g_esc[MAXE];

__device__ __forceinline__ __half2 h2tanh_fast(__half2 x) {
    uint32_t xi = *(uint32_t*)&x, yi;
    asm("tanh.approx.f16x2 %0, %1;" : "=r"(yi) : "r"(xi));
    return *(__half2*)&yi;
}

// ---------------- packing ----------------
__global__ void pack_w2_kernel(const float* __restrict__ Wxi) {
    int idx = blockIdx.x * blockDim.x + threadIdx.x;
    if (idx >= LNF * NPQ) return;
    int k = idx / NPQ, j = idx - k * NPQ;
    float v = (j < 1024) ? Wxi[k * 1024 + j] : Wxi[(k + LNF) * 1024 + (j - 1024)];
    g_W2b[idx] = __float2bfloat16(v);
}

__global__ void zero_kernel(int V) {
    int idx = blockIdx.x * blockDim.x + threadIdx.x;
    if (idx < V) g_cnt[idx] = 0;
}

// ---------------- CSR build ----------------
__global__ void count_kernel(const int* __restrict__ Xn, int E) {
    int e = blockIdx.x * blockDim.x + threadIdx.x;
    if (e < E) atomicAdd(&g_cnt[Xn[e]], 1);
}

// hierarchical scan: block sums -> scan partials -> per-block rescan
__global__ __launch_bounds__(SCAN_BLK) void scan1_kernel(int V) {
    __shared__ int s[SCAN_BLK];
    int i = blockIdx.x * SCAN_BLK + threadIdx.x;
    s[threadIdx.x] = (i < V) ? g_cnt[i] : 0;
    __syncthreads();
#pragma unroll
    for (int off = SCAN_BLK / 2; off > 0; off >>= 1) {
        if (threadIdx.x < off) s[threadIdx.x] += s[threadIdx.x + off];
        __syncthreads();
    }
    if (threadIdx.x == 0) g_bsum[blockIdx.x] = s[0];
}

__global__ __launch_bounds__(128) void scan2_kernel(int nb, int V) {
    __shared__ int s[128];
    int t = threadIdx.x;
    int v = (t < nb) ? g_bsum[t] : 0;
    s[t] = v;
    __syncthreads();
#pragma unroll
    for (int off = 1; off < 128; off <<= 1) {
        int x = (t >= off) ? s[t - off] : 0;
        __syncthreads();
        s[t] += x;
        __syncthreads();
    }
    if (t < nb) g_bsum[t] = s[t] - v;        // exclusive
    if (t == 127) g_off[V] = s[127];          // total
}

__global__ __launch_bounds__(SCAN_BLK) void scan3_kernel(int V) {
    __shared__ int s[SCAN_BLK];
    int i = blockIdx.x * SCAN_BLK + threadIdx.x;
    int v = (i < V) ? g_cnt[i] : 0;
    s[threadIdx.x] = v;
    __syncthreads();
#pragma unroll
    for (int off = 1; off < SCAN_BLK; off <<= 1) {
        int x = (threadIdx.x >= off) ? s[threadIdx.x - off] : 0;
        __syncthreads();
        s[threadIdx.x] += x;
        __syncthreads();
    }
    if (i < V) {
        g_off[i]  = g_bsum[blockIdx.x] + s[threadIdx.x] - v;   // exclusive
        g_fill[i] = 0;
    }
}

__global__ void fill_kernel(const int* __restrict__ Xn, const int* __restrict__ Xe,
                            const float* __restrict__ dg, int E) {
    int e = blockIdx.x * blockDim.x + threadIdx.x;
    if (e >= E) return;
    int u = Xn[e];
    int pos = g_off[u] + atomicAdd(&g_fill[u], 1);
    g_ev[pos]  = Xe[e];
    g_esc[pos] = MU_OVER_S / dg[e];
}

// ---------------- bf16 MMA GEMM: PQ[M x 2048] = featbf[M x 128] @ W2b ----------------
#define AS_STRIDE 136
#define SMEM_B_OFF (128 * AS_STRIDE)
#define GEMM_SMEM_BYTES (2 * 128 * AS_STRIDE * 2)

__device__ __forceinline__ void ldsm_x4(uint32_t& r0, uint32_t& r1, uint32_t& r2, uint32_t& r3,
                                        uint32_t addr) {
    asm volatile("ldmatrix.sync.aligned.m8n8.x4.shared.b16 {%0,%1,%2,%3}, [%4];"
                 : "=r"(r0), "=r"(r1), "=r"(r2), "=r"(r3) : "r"(addr));
}
__device__ __forceinline__ void ldsm_x4_t(uint32_t& r0, uint32_t& r1, uint32_t& r2, uint32_t& r3,
                                          uint32_t addr) {
    asm volatile("ldmatrix.sync.aligned.m8n8.x4.trans.shared.b16 {%0,%1,%2,%3}, [%4];"
                 : "=r"(r0), "=r"(r1), "=r"(r2), "=r"(r3) : "r"(addr));
}
__device__ __forceinline__ void mma_bf16(float* c, const uint32_t* a, uint32_t b0, uint32_t b1) {
    asm volatile(
        "mma.sync.aligned.m16n8k16.row.col.f32.bf16.bf16.f32 "
        "{%0,%1,%2,%3}, {%4,%5,%6,%7}, {%8,%9}, {%0,%1,%2,%3};\n"
        : "+f"(c[0]), "+f"(c[1]), "+f"(c[2]), "+f"(c[3])
        : "r"(a[0]), "r"(a[1]), "r"(a[2]), "r"(a[3]), "r"(b0), "r"(b1));
}
__device__ __forceinline__ void cp_async16(uint32_t saddr, const void* gaddr) {
    asm volatile("cp.async.cg.shared.global [%0], [%1], 16;" :: "r"(saddr), "l"(gaddr));
}

__global__ __launch_bounds__(256) void gemm_bf16_kernel(const float* __restrict__ bxi, int M) {
    extern __shared__ __nv_bfloat16 smem[];

    const int tid  = threadIdx.x;
    const int warp = tid >> 5;
    const int lane = tid & 31;
    const int g    = lane >> 2;
    const int t4   = lane & 3;
    const int wm   = warp & 3;
    const int wn   = warp >> 2;
    const int row0 = blockIdx.y * 128;
    const int col0 = blockIdx.x * 128;

    uint32_t smem_base;
    asm("{ .reg .u64 t; cvta.to.shared.u64 t, %1; cvt.u32.u64 %0, t; }"
        : "=r"(smem_base) : "l"(smem));

#pragma unroll
    for (int i = 0; i < 8; ++i) {
        int c = tid + i * 256;
        int r = c >> 4;
        int seg = c & 15;
        int grow = row0 + r; if (grow >= M) grow = M - 1;
        cp_async16(smem_base + (uint32_t)(r * AS_STRIDE + seg * 8) * 2,
                   g_fb + (size_t)grow * LNF + seg * 8);
        cp_async16(smem_base + (uint32_t)(SMEM_B_OFF + r * AS_STRIDE + seg * 8) * 2,
                   g_W2b + (size_t)r * NPQ + col0 + seg * 8);
    }
    asm volatile("cp.async.commit_group;");
    asm volatile("cp.async.wait_group 0;");
    __syncthreads();

    float acc[2][8][4];
#pragma unroll
    for (int mt = 0; mt < 2; ++mt)
#pragma unroll
        for (int nt = 0; nt < 8; ++nt)
#pragma unroll
            for (int r = 0; r < 4; ++r) acc[mt][nt][r] = 0.0f;

#pragma unroll
    for (int ks = 0; ks < 8; ++ks) {
        const int kb = ks * 16;
        uint32_t a[2][4];
#pragma unroll
        for (int mt = 0; mt < 2; ++mt) {
            int ar = wm * 32 + mt * 16;
            uint32_t addr = smem_base +
                (uint32_t)((ar + (lane & 15)) * AS_STRIDE + kb + ((lane >> 4) << 3)) * 2;
            ldsm_x4(a[mt][0], a[mt][1], a[mt][2], a[mt][3], addr);
        }
#pragma unroll
        for (int np = 0; np < 4; ++np) {
            int nc = wn * 64 + np * 16;
            uint32_t b0, b1, b2, b3;
            uint32_t addr = smem_base +
                (uint32_t)(SMEM_B_OFF + (kb + (lane & 15)) * AS_STRIDE + nc + ((lane >> 4) << 3)) * 2;
            ldsm_x4_t(b0, b1, b2, b3, addr);
#pragma unroll
            for (int mt = 0; mt < 2; ++mt) {
                mma_bf16(acc[mt][np * 2],     a[mt], b0, b1);
                mma_bf16(acc[mt][np * 2 + 1], a[mt], b2, b3);
            }
        }
    }

#pragma unroll
    for (int mt = 0; mt < 2; ++mt) {
        int rlo = row0 + wm * 32 + mt * 16 + g;
#pragma unroll
        for (int nt = 0; nt < 8; ++nt) {
            int c = col0 + wn * 64 + nt * 8 + 2 * t4;
            float b0 = 0.f, b1 = 0.f;
            if (c < 1024) { b0 = __ldg(&bxi[c]); b1 = __ldg(&bxi[c + 1]); }
            if (rlo < M)
                __stcs((__half2*)(g_PQh + (size_t)rlo * NPQ + c),
                       __floats2half2_rn(acc[mt][nt][0] + b0, acc[mt][nt][1] + b1));
            if (rlo + 8 < M)
                __stcs((__half2*)(g_PQh + (size_t)(rlo + 8) * NPQ + c),
                       __floats2half2_rn(acc[mt][nt][2] + b0, acc[mt][nt][3] + b1));
        }
    }
}

// ---------------- R kernel (fp32) + fused feat->bf16 conversion ----------------
#define RNODES 48
__global__ __launch_bounds__(256) void r_kernel(const float* __restrict__ feat,
                                                const float* __restrict__ Wrou,
                                                const float* __restrict__ brou, int V) {
    __shared__ float Ws[LNF * SS];
    __shared__ float fr[RNODES * LNF];
    const int tid = threadIdx.x;
    const int n0 = blockIdx.x * RNODES;

    for (int i = tid; i < LNF * SS; i += 256) Ws[i] = Wrou[i];
    for (int i = tid; i < RNODES * LNF / 4; i += 256) {
        int node = n0 + (i * 4) / LNF;
        if (node >= V) node = V - 1;
        int k = (i * 4) & (LNF - 1);
        *(float4*)&fr[i * 4] = *(const float4*)(feat + (size_t)node * LNF + k);
    }
    __syncthreads();

    for (int i = tid; i < RNODES * LNF / 2; i += 256) {
        int node = n0 + (i * 2) / LNF;
        if (node < V) {
            int k = (i * 2) & (LNF - 1);
            ((__nv_bfloat162*)(g_fb + (size_t)node * LNF + k))[0] =
                __floats2bfloat162_rn(fr[i * 2], fr[i * 2 + 1]);
        }
    }

    const int warp = tid >> 5, lane = tid & 31;
    float acc[6];
#pragma unroll
    for (int i = 0; i < 6; ++i) acc[i] = 0.0f;
    const float* fbase = &fr[warp * 6 * LNF];
#pragma unroll 16
    for (int k = 0; k < LNF; ++k) {
        float wv = Ws[k * SS + lane];
#pragma unroll
        for (int i = 0; i < 6; ++i) acc[i] = fmaf(fbase[i * LNF + k], wv, acc[i]);
    }
    float bb = brou[lane];
#pragma unroll
    for (int i = 0; i < 6; ++i) {
        int node = n0 + warp * 6 + i;
        if (node < V) g_R[node * SS + lane] = tanhf(acc[i] + bb);
    }
}

// ---------------- edge kernel: one warp per node, half of the S-rows per pass ----------------
__global__ __launch_bounds__(256) void edge_half_kernel(int V, int pass) {
    __shared__ float rs[8][SS];
    const int warp = threadIdx.x >> 5;
    const int lane = threadIdx.x & 31;
    const int u = blockIdx.x * 8 + warp;
    if (u >= V) return;
    const int n = g_cnt[u];
    if (n == 0) return;
    const int start = g_off[u];

    rs[warp][lane] = g_R[u * SS + lane];
    __syncwarp();

    const int row = lane >> 1;            // 0..15 local output row
    const int jh  = (lane & 1) * 16;      // j offset 0 or 16
    const size_t eoff = (size_t)pass * 512 + row * 32 + jh;

    // R slice in registers (16 values this lane contracts against)
    float rloc[16];
#pragma unroll
    for (int i = 0; i < 16; ++i) rloc[i] = rs[warp][jh + i];

    const uint4 pA = __ldcs((const uint4*)(g_PQh + (size_t)u * NPQ + eoff));
    const uint4 pB = __ldcs((const uint4*)(g_PQh + (size_t)u * NPQ + eoff + 8));

    float racc = 0.0f;
    for (int e = start; e < start + n; ++e) {
        const int v = __ldcs(&g_ev[e]);
        const float sc = __ldcs(&g_esc[e]);
        const __half* qrow = g_PQh + (size_t)v * NPQ + 1024 + eoff;
        uint4 qA = *(const uint4*)qrow;
        uint4 qB = *(const uint4*)(qrow + 8);

        float partial = 0.0f;
        const __half2* ph = (const __half2*)&pA;
        const __half2* qh = (const __half2*)&qA;
#pragma unroll
        for (int k = 0; k < 4; ++k) {
            float2 t = __half22float2(h2tanh_fast(__hadd2(ph[k], qh[k])));
            partial = fmaf(t.x, rloc[2 * k],     partial);
            partial = fmaf(t.y, rloc[2 * k + 1], partial);
        }
        ph = (const __half2*)&pB; qh = (const __half2*)&qB;
#pragma unroll
        for (int k = 0; k < 4; ++k) {
            float2 t = __half22float2(h2tanh_fast(__hadd2(ph[k], qh[k])));
            partial = fmaf(t.x, rloc[8 + 2 * k],     partial);
            partial = fmaf(t.y, rloc[8 + 2 * k + 1], partial);
        }
        racc = fmaf(partial, sc, racc);
    }

    racc += __shfl_down_sync(0xffffffffu, racc, 1, 2);
    if ((lane & 1) == 0)
        g_hacc[u * SS + pass * 16 + row] = racc;
}

// ---------------- output ----------------
__global__ __launch_bounds__(256) void out_kernel(const float* __restrict__ Wout,
                                                  const float* __restrict__ bout,
                                                  float* __restrict__ out, int V) {
    int gtid = blockIdx.x * blockDim.x + threadIdx.x;
    int vtx = gtid >> 5;
    int lane = threadIdx.x & 31;
    if (vtx >= V) return;

    float c = (float)g_cnt[vtx];
    float Hf = (c > 0.0f) ? c * (g_hacc[vtx * SS + lane] + g_R[vtx * SS + lane]) : 0.0f;

    float mine = 0.0f;
    float logits[CC];
#pragma unroll
    for (int j = 0; j < CC; ++j) {
        float p = Hf * Wout[lane * CC + j];
#pragma unroll
        for (int off = 16; off > 0; off >>= 1)
            p += __shfl_xor_sync(0xffffffffu, p, off);
        logits[j] = p + bout[j];
        if (j == lane) mine = logits[j];
    }
    float m = logits[0];
#pragma unroll
    for (int j = 1; j < CC; ++j) m = fmaxf(m, logits[j]);
    float se = 0.0f;
#pragma unroll
    for (int j = 0; j < CC; ++j) se += expf(logits[j] - m);
    float lse = m + logf(se);

    if (lane < CC) out[(size_t)vtx * CC + lane] = mine - lse;
}

// ---------------- launch ----------------
extern "C" void kernel_launch(void* const* d_in, const int* in_sizes, int n_in,
                              void* d_out, int out_size) {
    const float* feat = (const float*)d_in[0];
    const int*   Xn   = (const int*)d_in[1];
    const int*   Xe   = (const int*)d_in[2];
    const float* dg   = (const float*)d_in[3];
    const float* Wxi  = (const float*)d_in[4];
    const float* bxi  = (const float*)d_in[5];
    const float* Wrou = (const float*)d_in[6];
    const float* brou = (const float*)d_in[7];
    const float* Wout = (const float*)d_in[8];
    const float* bout = (const float*)d_in[9];
    float* out = (float*)d_out;

    const int V = in_sizes[0] / LNF;
    const int E = in_sizes[1];
    const int nb = (V + SCAN_BLK - 1) / SCAN_BLK;

    cudaFuncSetAttribute(gemm_bf16_kernel,
                         cudaFuncAttributeMaxDynamicSharedMemorySize, GEMM_SMEM_BYTES);

    pack_w2_kernel<<<(LNF * NPQ + 255) / 256, 256>>>(Wxi);
    zero_kernel<<<(V + 255) / 256, 256>>>(V);
    count_kernel<<<(E + 255) / 256, 256>>>(Xn, E);
    scan1_kernel<<<nb, SCAN_BLK>>>(V);
    scan2_kernel<<<1, 128>>>(nb, V);
    scan3_kernel<<<nb, SCAN_BLK>>>(V);
    fill_kernel<<<(E + 255) / 256, 256>>>(Xn, Xe, dg, E);

    r_kernel<<<(V + RNODES - 1) / RNODES, 256>>>(feat, Wrou, brou, V);   // also writes g_fb

    dim3 ggrid(NPQ / 128, (V + 127) / 128);
    gemm_bf16_kernel<<<ggrid, 256, GEMM_SMEM_BYTES>>>(bxi, V);

    edge_half_kernel<<<(V + 7) / 8, 256>>>(V, 0);
    edge_half_kernel<<<(V + 7) / 8, 256>>>(V, 1);
    out_kernel<<<(V * 32 + 255) / 256, 256>>>(Wout, bout, out, V);
}